// round 1
// baseline (speedup 1.0000x reference)
#include <cuda_runtime.h>

#define N_NODES 100000
#define N_EDGES 1600000
#define F 128
#define NGRAPH 64

// ---------------- scratch (device globals; no allocations) ----------------
__device__ float g_dinv[N_NODES];
__device__ int   g_deg[N_NODES];
__device__ float g_xw [(size_t)N_NODES * F];
__device__ float g_agg[(size_t)N_NODES * F];
__device__ float g_h  [(size_t)N_NODES * F];
__device__ float g_pool[NGRAPH * F];

// ---------------- helpers ----------------
__device__ __forceinline__ void fma2(unsigned long long& c, unsigned long long a,
                                     unsigned long long b) {
    asm("fma.rn.f32x2 %0, %1, %2, %0;" : "+l"(c) : "l"(a), "l"(b));
}
__device__ __forceinline__ unsigned long long pack2(float a) {
    unsigned long long r;
    asm("mov.b64 %0, {%1, %1};" : "=l"(r) : "f"(a));
    return r;
}
__device__ __forceinline__ float2 unpack2(unsigned long long v) {
    float2 r;
    asm("mov.b64 {%0, %1}, %2;" : "=f"(r.x), "=f"(r.y) : "l"(v));
    return r;
}

// ---------------- zero kernels ----------------
__global__ void k_zero_f4(float4* p, int n4) {
    int i = blockIdx.x * blockDim.x + threadIdx.x;
    int stride = gridDim.x * blockDim.x;
    float4 z = make_float4(0.f, 0.f, 0.f, 0.f);
    for (; i < n4; i += stride) p[i] = z;
}
__global__ void k_zero_i(int* p, int n) {
    int i = blockIdx.x * blockDim.x + threadIdx.x;
    int stride = gridDim.x * blockDim.x;
    for (; i < n; i += stride) p[i] = 0;
}

// ---------------- degree / dinv ----------------
__global__ void k_degree(const int* __restrict__ col) {
    int i = blockIdx.x * blockDim.x + threadIdx.x;
    int stride = gridDim.x * blockDim.x;
    for (; i < N_EDGES; i += stride) atomicAdd(&g_deg[col[i]], 1);
}
__global__ void k_dinv() {
    int i = blockIdx.x * blockDim.x + threadIdx.x;
    if (i < N_NODES) g_dinv[i] = rsqrtf((float)g_deg[i] + 2.0f);
}

// ---------------- GEMM: C[M,128] = A[M,128] @ W[128,128] (fp32, f32x2 packed) ----
// BM=64 rows per block, 256 threads, thread tile 4 rows x 8 cols (4 packed f32x2).
#define GEMM_SMEM ((64 * 129 + 128 * 128) * 4)
__global__ void k_gemm(const float* __restrict__ A, const float* __restrict__ W,
                       float* __restrict__ C, int M) {
    extern __shared__ float sm[];
    float* As = sm;               // 64 x 129 (padded)
    float* Ws = sm + 64 * 129;    // 128 x 128
    const int t  = threadIdx.x;   // 256 threads
    const int m0 = blockIdx.x * 64;

    // load W (128x128) -> smem
    #pragma unroll 4
    for (int i = t; i < 128 * 32; i += 256)
        ((float4*)Ws)[i] = ((const float4*)W)[i];

    // load A tile (64x128) -> smem with pad 129
    for (int i = t; i < 64 * 32; i += 256) {
        int r = i >> 5, c = i & 31;
        float4 v = make_float4(0.f, 0.f, 0.f, 0.f);
        if (m0 + r < M) v = ((const float4*)(A + (size_t)(m0 + r) * F))[c];
        float* p = As + r * 129 + c * 4;
        p[0] = v.x; p[1] = v.y; p[2] = v.z; p[3] = v.w;
    }
    __syncthreads();

    const int tx = t & 15;   // col group: cols tx*8 .. tx*8+7
    const int ty = t >> 4;   // row group: rows ty*4 .. ty*4+3

    unsigned long long acc[4][4];
    #pragma unroll
    for (int i = 0; i < 4; i++)
        #pragma unroll
        for (int j = 0; j < 4; j++) acc[i][j] = 0ULL;

    const float* a_base = As + (ty * 4) * 129;
    const float* b_base = Ws + tx * 8;

    #pragma unroll 4
    for (int k = 0; k < 128; k++) {
        unsigned long long pa0 = pack2(a_base[k]);
        unsigned long long pa1 = pack2(a_base[129 + k]);
        unsigned long long pa2 = pack2(a_base[2 * 129 + k]);
        unsigned long long pa3 = pack2(a_base[3 * 129 + k]);
        const ulonglong2* bp = (const ulonglong2*)(b_base + k * 128);
        ulonglong2 b01 = bp[0];  // cols 0..3 (two packed pairs)
        ulonglong2 b23 = bp[1];  // cols 4..7
        fma2(acc[0][0], pa0, b01.x); fma2(acc[0][1], pa0, b01.y);
        fma2(acc[0][2], pa0, b23.x); fma2(acc[0][3], pa0, b23.y);
        fma2(acc[1][0], pa1, b01.x); fma2(acc[1][1], pa1, b01.y);
        fma2(acc[1][2], pa1, b23.x); fma2(acc[1][3], pa1, b23.y);
        fma2(acc[2][0], pa2, b01.x); fma2(acc[2][1], pa2, b01.y);
        fma2(acc[2][2], pa2, b23.x); fma2(acc[2][3], pa2, b23.y);
        fma2(acc[3][0], pa3, b01.x); fma2(acc[3][1], pa3, b01.y);
        fma2(acc[3][2], pa3, b23.x); fma2(acc[3][3], pa3, b23.y);
    }

    #pragma unroll
    for (int i = 0; i < 4; i++) {
        int r = m0 + ty * 4 + i;
        if (r < M) {
            float2 v0 = unpack2(acc[i][0]);
            float2 v1 = unpack2(acc[i][1]);
            float2 v2 = unpack2(acc[i][2]);
            float2 v3 = unpack2(acc[i][3]);
            float4* dst = (float4*)(C + (size_t)r * F + tx * 8);
            dst[0] = make_float4(v0.x, v0.y, v1.x, v1.y);
            dst[1] = make_float4(v2.x, v2.y, v3.x, v3.y);
        }
    }
}

// ---------------- edge scatter: agg[col] += dinv[row]*dinv[col] * xw[row] ----
// warp per edge; lane owns one float4 (4 features); vectorized red.global.add
__global__ void k_edge(const int* __restrict__ row, const int* __restrict__ col,
                       const float* __restrict__ src, float* __restrict__ dst) {
    int warp  = (blockIdx.x * blockDim.x + threadIdx.x) >> 5;
    int lane  = threadIdx.x & 31;
    int nwarp = (gridDim.x * blockDim.x) >> 5;
    for (int e = warp; e < N_EDGES; e += nwarp) {
        int r = row[e];
        int c = col[e];
        float nrm = g_dinv[r] * g_dinv[c];
        float4 v = ((const float4*)(src + ((size_t)r << 7)))[lane];
        v.x *= nrm; v.y *= nrm; v.z *= nrm; v.w *= nrm;
        float* addr = dst + ((size_t)c << 7) + lane * 4;
        asm volatile("red.global.add.v4.f32 [%0], {%1, %2, %3, %4};"
                     :: "l"(addr), "f"(v.x), "f"(v.y), "f"(v.z), "f"(v.w)
                     : "memory");
    }
}

// ---------------- post layer 1: h = relu(agg + 2*dinv^2*xw + b) ----------------
__global__ void k_post(const float* __restrict__ agg, const float* __restrict__ xw,
                       const float* __restrict__ b, float* __restrict__ h) {
    int i = blockIdx.x * blockDim.x + threadIdx.x;
    int stride = gridDim.x * blockDim.x;
    const int n4 = N_NODES * (F / 4);
    for (; i < n4; i += stride) {
        int node = i >> 5;
        int c4   = i & 31;
        float d = g_dinv[node];
        float s = 2.f * d * d;
        float4 ag = ((const float4*)agg)[i];
        float4 xv = ((const float4*)xw)[i];
        float4 bv = ((const float4*)b)[c4];
        float4 o;
        o.x = fmaxf(fmaf(s, xv.x, ag.x) + bv.x, 0.f);
        o.y = fmaxf(fmaf(s, xv.y, ag.y) + bv.y, 0.f);
        o.z = fmaxf(fmaf(s, xv.z, ag.z) + bv.z, 0.f);
        o.w = fmaxf(fmaf(s, xv.w, ag.w) + bv.w, 0.f);
        ((float4*)h)[i] = o;
    }
}

// ---------------- post layer 2 + dropout + segment max pool (fused) ----------
// block = 128 threads (one per feature), handles 64 consecutive nodes.
// batch is sorted -> few segment flushes per block. Values >= 0 so int atomicMax
// on float bits is order-correct and 0-init is the identity.
__global__ void k_post2_pool(const float* __restrict__ agg, const float* __restrict__ xw,
                             const float* __restrict__ b2, const int* __restrict__ mask,
                             const int* __restrict__ batch) {
    int t  = threadIdx.x;           // feature
    int n0 = blockIdx.x * 64;
    float bb = b2[t];
    int cur = -1;
    float mx = 0.f;
    for (int i = 0; i < 64; i++) {
        int n = n0 + i;
        if (n >= N_NODES) break;
        int bid = batch[n];
        if (bid != cur) {
            if (cur >= 0) atomicMax((int*)&g_pool[cur * F + t], __float_as_int(mx));
            cur = bid;
            mx = 0.f;
        }
        float d = g_dinv[n];
        size_t idx = (size_t)n * F + t;
        float v = fmaf(2.f * d * d, xw[idx], agg[idx]) + bb;
        v = fmaxf(v, 0.f);
        v *= (float)(mask[idx] << 1);   // dropout: *mask*2
        mx = fmaxf(mx, v);
    }
    if (cur >= 0) atomicMax((int*)&g_pool[cur * F + t], __float_as_int(mx));
}

// ---------------- head: relu(pool @ Wm + bm) @ Wf + bf -> out[64,32] ----------
__global__ void k_head(const float* __restrict__ Wm, const float* __restrict__ bm,
                       const float* __restrict__ Wf, const float* __restrict__ bf,
                       float* __restrict__ out) {
    __shared__ float sh[NGRAPH * F];   // 32 KB hidden
    int t = threadIdx.x;               // 256
    for (int i = t; i < NGRAPH * F; i += 256) {
        int g = i >> 7, f = i & 127;
        float acc = bm[f];
        const float* pg = g_pool + g * F;
        #pragma unroll 8
        for (int k = 0; k < 128; k++) acc = fmaf(pg[k], Wm[k * F + f], acc);
        sh[i] = fmaxf(acc, 0.f);
    }
    __syncthreads();
    for (int i = t; i < NGRAPH * 32; i += 256) {
        int g = i >> 5, o = i & 31;
        float acc = bf[o];
        const float* hg = sh + g * F;
        #pragma unroll 8
        for (int k = 0; k < 128; k++) acc = fmaf(hg[k], Wf[k * 32 + o], acc);
        out[i] = acc;
    }
}

// ---------------- launch ----------------
extern "C" void kernel_launch(void* const* d_in, const int* in_sizes, int n_in,
                              void* d_out, int out_size) {
    const float* x     = (const float*)d_in[0];
    const int*   ei    = (const int*)d_in[1];
    const int*   batch = (const int*)d_in[2];
    const int*   mask  = (const int*)d_in[3];
    const float* W1    = (const float*)d_in[4];
    const float* b1    = (const float*)d_in[5];
    const float* W2    = (const float*)d_in[6];
    const float* b2    = (const float*)d_in[7];
    const float* Wm    = (const float*)d_in[8];
    const float* bm    = (const float*)d_in[9];
    const float* Wf    = (const float*)d_in[10];
    const float* bf    = (const float*)d_in[11];
    float* out = (float*)d_out;

    float *xw, *agg, *h, *pool, *dinvp;
    int* deg;
    cudaGetSymbolAddress((void**)&xw,    g_xw);
    cudaGetSymbolAddress((void**)&agg,   g_agg);
    cudaGetSymbolAddress((void**)&h,     g_h);
    cudaGetSymbolAddress((void**)&pool,  g_pool);
    cudaGetSymbolAddress((void**)&dinvp, g_dinv);
    cudaGetSymbolAddress((void**)&deg,   g_deg);
    (void)dinvp; (void)in_sizes; (void)n_in; (void)out_size;

    cudaFuncSetAttribute(k_gemm, cudaFuncAttributeMaxDynamicSharedMemorySize, GEMM_SMEM);

    const int gemm_blocks = (N_NODES + 63) / 64;      // 1563
    const int pool_blocks = (N_NODES + 63) / 64;      // 1563
    const int NF4 = N_NODES * (F / 4);                // 3.2M float4

    const int* row = ei;
    const int* col = ei + N_EDGES;

    // degrees
    k_zero_i<<<256, 256>>>(deg, N_NODES);
    k_zero_f4<<<16, 256>>>((float4*)pool, NGRAPH * F / 4);
    k_degree<<<1184, 256>>>(col);
    k_dinv<<<(N_NODES + 255) / 256, 256>>>();

    // layer 1
    k_gemm<<<gemm_blocks, 256, GEMM_SMEM>>>(x, W1, xw, N_NODES);
    k_zero_f4<<<2048, 256>>>((float4*)agg, NF4);
    k_edge<<<1184, 256>>>(row, col, xw, agg);
    k_post<<<2048, 256>>>(agg, xw, b1, h);

    // layer 2
    k_gemm<<<gemm_blocks, 256, GEMM_SMEM>>>(h, W2, xw, N_NODES);
    k_zero_f4<<<2048, 256>>>((float4*)agg, NF4);
    k_edge<<<1184, 256>>>(row, col, xw, agg);

    // post2 + dropout + max-pool (fused)
    k_post2_pool<<<pool_blocks, 128>>>(agg, xw, b2, mask, batch);

    // MLP head
    k_head<<<1, 256>>>(Wm, bm, Wf, bf, out);
}